// round 4
// baseline (speedup 1.0000x reference)
#include <cuda_runtime.h>
#include <cuda_bf16.h>
#include <cstdint>
#include <cstddef>

#define NN   4096
#define FIN  512
#define DH   64
#define NH   8
#define NC   16
#define KH   2
#define MAXNBR 512

typedef unsigned long long ull;

// ---------------- scratch ----------------------------------------------------
__device__ __nv_bfloat162 g_Whb[(size_t)NH * NN * (DH / 2)]; // [H,N,D] bf16 (4 MB)
__device__ float g_f1[NH * NN];
__device__ float g_f2[NH * NN];
__device__ float g_Who[NN * NC];
__device__ float g_WoutT[NC * FIN];
__device__ float g_g1[NN];
__device__ float g_g2[NN];
__device__ int   g_nbr[(size_t)KH * NN * MAXNBR];
__device__ int   g_cnt[KH * NN];

// ---------------- f32x2 helpers ----------------------------------------------
__device__ __forceinline__ void fma2(ull& d, ull a, ull b) {
    asm("fma.rn.f32x2 %0, %1, %2, %0;" : "+l"(d) : "l"(a), "l"(b));
}
__device__ __forceinline__ ull pack2(float x, float y) {
    ull r; asm("mov.b64 %0, {%1, %2};" : "=l"(r) : "f"(x), "f"(y)); return r;
}
__device__ __forceinline__ float2 unpack2(ull v) {
    float2 r; asm("mov.b64 {%0, %1}, %2;" : "=f"(r.x), "=f"(r.y) : "l"(v)); return r;
}

// ---------------- prep: zero Who + transpose W_out -----------------------------
__global__ void __launch_bounds__(256) prep_kernel(const float* __restrict__ Wout) {
    int t = blockIdx.x * 256 + threadIdx.x;      // 64 blocks x 256 = 16384
    ((float4*)g_Who)[t] = make_float4(0.f, 0.f, 0.f, 0.f);
    if (t < FIN * NC) {
        int c = t & 15, k = t >> 4;
        g_WoutT[c * FIN + k] = Wout[t];
    }
}

// ---------------- neighbor list build (detection inlined) ---------------------
__global__ void __launch_bounds__(256) build_nbr_kernel(const void* m) {
    __shared__ int mode_s;
    if (threadIdx.x < 32) {
        bool okb = ((const unsigned char*)m)[(size_t)threadIdx.x * NN + threadIdx.x] == 1;
        unsigned bal = __ballot_sync(0xffffffffu, okb);
        if (threadIdx.x == 0) mode_s = (bal == 0xffffffffu) ? 0 : 1;
    }
    __syncthreads();
    const int mode = mode_s;

    const int gw   = (blockIdx.x * blockDim.x + threadIdx.x) >> 5;
    const int lane = threadIdx.x & 31;
    if (gw >= KH * NN) return;
    int* nb = g_nbr + (size_t)gw * MAXNBR;
    int cnt = 0;

    if (mode == 0) {
        const uint4* p = (const uint4*)((const unsigned char*)m + (size_t)gw * NN);
#pragma unroll
        for (int it = 0; it < NN / 512; ++it) {
            uint4 v = p[it * 32 + lane];
            unsigned w[4] = {v.x, v.y, v.z, v.w};
            int base = it * 512 + lane * 16;
#pragma unroll
            for (int q = 0; q < 4; ++q)
#pragma unroll
                for (int bp = 0; bp < 4; ++bp) {
                    bool mv = ((w[q] >> (8 * bp)) & 0xffu) != 0u;
                    unsigned bal = __ballot_sync(0xffffffffu, mv);
                    if (mv) {
                        int pos = cnt + __popc(bal & ((1u << lane) - 1u));
                        if (pos < MAXNBR) nb[pos] = base + q * 4 + bp;
                    }
                    cnt += __popc(bal);
                }
        }
    } else {
        const uint4* p = (const uint4*)((const unsigned*)m + (size_t)gw * NN);
#pragma unroll 4
        for (int it = 0; it < NN / 128; ++it) {
            uint4 v = p[it * 32 + lane];
            unsigned w[4] = {v.x, v.y, v.z, v.w};
            int base = it * 128 + lane * 4;
#pragma unroll
            for (int q = 0; q < 4; ++q) {
                bool mv = (w[q] != 0u);
                unsigned bal = __ballot_sync(0xffffffffu, mv);
                if (mv) {
                    int pos = cnt + __popc(bal & ((1u << lane) - 1u));
                    if (pos < MAXNBR) nb[pos] = base + q;
                }
                cnt += __popc(bal);
            }
        }
    }
    if (lane == 0) g_cnt[gw] = cnt < MAXNBR ? cnt : MAXNBR;
}

// ---------------- Wh = x @ W (bf16 out) + fused f1/f2, FFMA2 inner loop -------
#define GBM 128
#define GBK 32
__global__ void __launch_bounds__(128) wh_gemm_kernel(
        const float* __restrict__ x, const float* __restrict__ W,
        const float* __restrict__ a1v, const float* __restrict__ a2v) {
    const int h = blockIdx.y, row0 = blockIdx.x * GBM;
    const int tid = threadIdx.x;
    const int tx = tid & 7;
    const int ty = tid >> 3;

    __shared__ ull   xsd[GBK][GBM];
    __shared__ float ws [GBK][DH];

    ull acc[8][4];
#pragma unroll
    for (int i = 0; i < 8; ++i)
#pragma unroll
        for (int j = 0; j < 4; ++j) acc[i][j] = 0ULL;

    for (int k0 = 0; k0 < FIN; k0 += GBK) {
#pragma unroll
        for (int pass = 0; pass < 4; ++pass) {
            int r = pass * 32 + (tid >> 2);
            int seg = tid & 3;
            const float4* xp = (const float4*)(x + (size_t)(row0 + r) * FIN + k0 + seg * 8);
            float4 v0 = xp[0], v1 = xp[1];
            xsd[seg * 8 + 0][r] = pack2(v0.x, v0.x);
            xsd[seg * 8 + 1][r] = pack2(v0.y, v0.y);
            xsd[seg * 8 + 2][r] = pack2(v0.z, v0.z);
            xsd[seg * 8 + 3][r] = pack2(v0.w, v0.w);
            xsd[seg * 8 + 4][r] = pack2(v1.x, v1.x);
            xsd[seg * 8 + 5][r] = pack2(v1.y, v1.y);
            xsd[seg * 8 + 6][r] = pack2(v1.z, v1.z);
            xsd[seg * 8 + 7][r] = pack2(v1.w, v1.w);
        }
        {
            int s = tid;
#pragma unroll
            for (int rep = 0; rep < 4; ++rep, s += 128) {
                int kk = s >> 4, c4 = (s & 15) * 4;
                float4 v = *(const float4*)(W + ((size_t)h * FIN + k0 + kk) * DH + c4);
                *(float4*)&ws[kk][c4] = v;
            }
        }
        __syncthreads();
#pragma unroll
        for (int kk = 0; kk < GBK; ++kk) {
            ull a[8];
            *(ulonglong2*)&a[0] = *(const ulonglong2*)&xsd[kk][ty * 8 + 0];
            *(ulonglong2*)&a[2] = *(const ulonglong2*)&xsd[kk][ty * 8 + 2];
            *(ulonglong2*)&a[4] = *(const ulonglong2*)&xsd[kk][ty * 8 + 4];
            *(ulonglong2*)&a[6] = *(const ulonglong2*)&xsd[kk][ty * 8 + 6];
            ull b[4];
            *(ulonglong2*)&b[0] = *(const ulonglong2*)&ws[kk][tx * 8 + 0];
            *(ulonglong2*)&b[2] = *(const ulonglong2*)&ws[kk][tx * 8 + 4];
#pragma unroll
            for (int i = 0; i < 8; ++i)
#pragma unroll
                for (int j = 0; j < 4; ++j)
                    fma2(acc[i][j], a[i], b[j]);
        }
        __syncthreads();
    }

    const float* A1 = a1v + h * DH + tx * 8;
    const float* A2 = a2v + h * DH + tx * 8;
    float a1r[8], a2r[8];
#pragma unroll
    for (int c = 0; c < 8; ++c) { a1r[c] = A1[c]; a2r[c] = A2[c]; }

    float* f1s = (float*)xsd;
    float* f2s = f1s + 1024;

#pragma unroll
    for (int i = 0; i < 8; ++i) {
        float v[8];
#pragma unroll
        for (int j = 0; j < 4; ++j) {
            float2 u = unpack2(acc[i][j]);
            v[2 * j] = u.x; v[2 * j + 1] = u.y;
        }
        int row = row0 + ty * 8 + i;
        __nv_bfloat162* dst = g_Whb + ((size_t)h * NN + row) * 32 + tx * 4;
        dst[0] = __floats2bfloat162_rn(v[0], v[1]);
        dst[1] = __floats2bfloat162_rn(v[2], v[3]);
        dst[2] = __floats2bfloat162_rn(v[4], v[5]);
        dst[3] = __floats2bfloat162_rn(v[6], v[7]);
        float p1 = 0.f, p2 = 0.f;
#pragma unroll
        for (int c = 0; c < 8; ++c) { p1 += v[c] * a1r[c]; p2 += v[c] * a2r[c]; }
        f1s[tx * 128 + ty * 8 + i] = p1;
        f2s[tx * 128 + ty * 8 + i] = p2;
    }
    __syncthreads();
    {
        int r = tid;
        float s1 = 0.f, s2 = 0.f;
#pragma unroll
        for (int g = 0; g < 8; ++g) { s1 += f1s[g * 128 + r]; s2 += f2s[g * 128 + r]; }
        g_f1[h * NN + row0 + r] = s1;
        g_f2[h * NN + row0 + r] = s2;
    }
}

// ---------------- layer-1: block per (h,n), 4 warps, fused Who atomics --------
__global__ void __launch_bounds__(128) gat1_kernel() {
    const int b = blockIdx.x;
    const int h = b >> 12;
    const int n = b & 4095;
    const int t = threadIdx.x, wi = t >> 5, lane = t & 31;
    const int q = lane & 15, half = lane >> 4;

    __shared__ ull    pd[MAXNBR];      // (exp, byte-offset) 4 KB
    __shared__ float  red[4];
    __shared__ float4 accs[4][16];
    __shared__ float  xh[DH];

    const float  f1v = g_f1[h * NN + n];
    const float* f2h = g_f2 + h * NN;
    const char*  whq = (const char*)(g_Whb + (size_t)h * NN * 32) + q * 8;

    float t0 = 0.f, t1 = 0.f, t2 = 0.f, t3 = 0.f;

#pragma unroll
    for (int hop = 0; hop < KH; ++hop) {
        const int  w   = hop * NN + n;
        const int  cnt = g_cnt[w];
        const int* nbg = g_nbr + (size_t)w * MAXNBR;

        // phase 1: e -> exp, packed (weight, offset), block sum (no max pass)
        float lsum = 0.f;
        for (int j = t; j < cnt; j += 128) {
            int nbj = __ldg(nbg + j);
            float v = f1v + __ldg(f2h + nbj);
            v = fmaxf(v, 0.2f * v);              // leakyrelu
            float ex = __expf(v);
            pd[j] = ((ull)(unsigned)(nbj << 7) << 32) | (ull)__float_as_uint(ex);
            lsum += ex;
        }
#pragma unroll
        for (int s = 16; s > 0; s >>= 1)
            lsum += __shfl_xor_sync(0xffffffffu, lsum, s);
        if (lane == 0) red[wi] = lsum;
        __syncthreads();
        const float scale = (hop ? 0.9f : 1.0f) / (red[0] + red[1] + red[2] + red[3]);

        // phase 2: half-warps gather 4 bf16 features per lane, 2 nbrs/warp-iter
        float a0 = 0.f, a1 = 0.f, a2 = 0.f, a3 = 0.f;
        for (int j = wi * 2 + half; j < cnt; j += 8) {
            ull pv = pd[j];
            float    p   = __uint_as_float((unsigned)pv);
            unsigned off = (unsigned)(pv >> 32);
            ull w2 = *(const ull*)(whq + off);
            unsigned wlo = (unsigned)w2, whi = (unsigned)(w2 >> 32);
            a0 += p * __uint_as_float(wlo << 16);
            a1 += p * __uint_as_float(wlo & 0xffff0000u);
            a2 += p * __uint_as_float(whi << 16);
            a3 += p * __uint_as_float(whi & 0xffff0000u);
        }
        t0 += scale * a0; t1 += scale * a1; t2 += scale * a2; t3 += scale * a3;
        __syncthreads();
    }

    // combine halves (features identical, neighbors partitioned)
    t0 += __shfl_xor_sync(0xffffffffu, t0, 16);
    t1 += __shfl_xor_sync(0xffffffffu, t1, 16);
    t2 += __shfl_xor_sync(0xffffffffu, t2, 16);
    t3 += __shfl_xor_sync(0xffffffffu, t3, 16);
    if (half == 0) accs[wi][q] = make_float4(t0, t1, t2, t3);
    __syncthreads();

    if (wi == 0) {
        if (half == 0) {
            float4 r0 = accs[0][q], r1 = accs[1][q], r2 = accs[2][q], r3 = accs[3][q];
            float v0 = r0.x + r1.x + r2.x + r3.x;
            float v1 = r0.y + r1.y + r2.y + r3.y;
            float v2 = r0.z + r1.z + r2.z + r3.z;
            float v3 = r0.w + r1.w + r2.w + r3.w;
            v0 = v0 > 0.f ? v0 : (__expf(v0) - 1.f);
            v1 = v1 > 0.f ? v1 : (__expf(v1) - 1.f);
            v2 = v2 > 0.f ? v2 : (__expf(v2) - 1.f);
            v3 = v3 > 0.f ? v3 : (__expf(v3) - 1.f);
            *(float4*)&xh[q * 4] = make_float4(v0, v1, v2, v3);
        }
        __syncwarp();
        if (half == 0) {
            // partial Who: class q gets dot(xh[0:64], WoutT[q, h*64:(h+1)*64])
            const float4* wt = (const float4*)(g_WoutT + q * FIN + h * DH);
            const float4* xv = (const float4*)xh;
            float s = 0.f;
#pragma unroll
            for (int d = 0; d < 16; ++d) {
                float4 a = xv[d], bw = wt[d];
                s += a.x * bw.x + a.y * bw.y + a.z * bw.z + a.w * bw.w;
            }
            atomicAdd(g_Who + (size_t)n * NC + q, s);
        }
    }
}

// ---------------- g1/g2 from completed Who -------------------------------------
__global__ void __launch_bounds__(256) g12_kernel(
        const float* __restrict__ ao1, const float* __restrict__ ao2) {
    int n = blockIdx.x * 256 + threadIdx.x;      // 16 blocks
    const float4* who = (const float4*)(g_Who + (size_t)n * NC);
    float s1 = 0.f, s2 = 0.f;
#pragma unroll
    for (int i = 0; i < 4; ++i) {
        float4 v = who[i];
        float4 a = ((const float4*)ao1)[i];
        float4 bq = ((const float4*)ao2)[i];
        s1 += v.x * a.x + v.y * a.y + v.z * a.z + v.w * a.w;
        s2 += v.x * bq.x + v.y * bq.y + v.z * bq.z + v.w * bq.w;
    }
    g_g1[n] = s1;
    g_g2[n] = s2;
}

// ---------------- output sparse attention + elu + log_softmax ------------------
__global__ void __launch_bounds__(128) out_kernel(float* __restrict__ out) {
    const int wi   = threadIdx.x >> 5;
    const int n    = blockIdx.x * 4 + wi;
    const int lane = threadIdx.x & 31;
    const int c    = lane & 15;
    const int half = lane >> 4;

    __shared__ ull pd[4][MAXNBR];

    const float g1v = g_g1[n];
    float acc = 0.f;

#pragma unroll
    for (int hop = 0; hop < KH; ++hop) {
        const int  w   = hop * NN + n;
        const int  cnt = g_cnt[w];
        const int* nbg = g_nbr + (size_t)w * MAXNBR;

        float lsum = 0.f;
        for (int j = lane; j < cnt; j += 32) {
            int nbj = nbg[j];
            float v = g1v + g_g2[nbj];
            v = fmaxf(v, 0.2f * v);
            float ex = __expf(v);
            pd[wi][j] = ((ull)(unsigned)(nbj << 6) << 32) | (ull)__float_as_uint(ex);
            lsum += ex;
        }
#pragma unroll
        for (int s = 16; s > 0; s >>= 1)
            lsum += __shfl_xor_sync(0xffffffffu, lsum, s);
        __syncwarp();

        const char* whoc = (const char*)g_Who + c * 4;
        float part = 0.f;
        for (int j = half; j < cnt; j += 2) {
            ull pv = pd[wi][j];
            float    p   = __uint_as_float((unsigned)pv);
            unsigned off = (unsigned)(pv >> 32);
            part += p * *(const float*)(whoc + off);
        }
        acc += ((hop ? 0.9f : 1.0f) / lsum) * part;
        __syncwarp();
    }
    acc += __shfl_xor_sync(0xffffffffu, acc, 16);

    float v = acc > 0.f ? acc : (__expf(acc) - 1.f);
    float mx = v;
#pragma unroll
    for (int s = 8; s > 0; s >>= 1)
        mx = fmaxf(mx, __shfl_xor_sync(0xffffffffu, mx, s));
    float ex = __expf(v - mx);
    float sum = ex;
#pragma unroll
    for (int s = 8; s > 0; s >>= 1)
        sum += __shfl_xor_sync(0xffffffffu, sum, s);
    if (lane < NC)
        out[(size_t)n * NC + lane] = v - mx - __logf(sum);
}

// ---------------- launch --------------------------------------------------------
extern "C" void kernel_launch(void* const* d_in, const int* in_sizes, int n_in,
                              void* d_out, int out_size) {
    const float* x      = (const float*)d_in[0];
    const void*  masks  = (const void*) d_in[1];
    const float* W      = (const float*)d_in[2];
    const float* a1     = (const float*)d_in[3];
    const float* a2     = (const float*)d_in[4];
    const float* W_out  = (const float*)d_in[5];
    const float* ao1    = (const float*)d_in[6];
    const float* ao2    = (const float*)d_in[7];
    float* out = (float*)d_out;

    prep_kernel<<<64, 256>>>(W_out);
    build_nbr_kernel<<<(KH * NN * 32) / 256, 256>>>(masks);
    wh_gemm_kernel<<<dim3(NN / GBM, NH), 128>>>(x, W, a1, a2);
    gat1_kernel<<<NH * NN, 128>>>();
    g12_kernel<<<NN / 256, 256>>>(ao1, ao2);
    out_kernel<<<NN / 4, 128>>>(out);
}